// round 15
// baseline (speedup 1.0000x reference)
#include <cuda_runtime.h>
#include <cuda_bf16.h>
#include <math.h>

// Problem constants
#define B_     64
#define S_     2048
#define D_     768
#define L_     2
#define POOL_  30
#define LEN_   5
#define TOPK_  5
#define SS_    16           // S split count
#define SCHUNK_ (S_ / SS_)  // 128

// Output layout (flattened tuple, fp32):
#define NB_ELEMS   (L_ * B_ * (TOPK_*LEN_) * D_)   // 2457600
#define OFF_SB     0
#define OFF_TB     (NB_ELEMS)
#define OFF_SSIM   (2 * NB_ELEMS)
#define OFF_TSIM   (OFF_SSIM + B_ * POOL_)
#define OFF_SRED   (OFF_TSIM + B_ * POOL_)
#define OFF_TRED   (OFF_SRED + 1)

// Device scratch
__device__ float g_partial[SS_ * B_ * D_];   // 3 MB partial sums
__device__ int   g_idx[2][B_ * TOPK_];       // [pool][b*5+k]
__device__ float g_stop[B_];
__device__ float g_ttop[B_];

__device__ __forceinline__ void l2_prefetch(const void* p) {
    asm volatile("prefetch.global.L2 [%0];" :: "l"(p));
}

// ---------------------------------------------------------------------------
// Kernel A: partial mean over S chunks.  grid (B, SS), block 192.
// R4 streaming body (32 regs); PDL trigger after the partial store.
// ---------------------------------------------------------------------------
__global__ void __launch_bounds__(192) k_mean_partial(const float* __restrict__ x) {
    int b  = blockIdx.x;
    int ss = blockIdx.y;
    int d4 = threadIdx.x;                     // 0..191, each owns 4 d's
    const float4* xp = reinterpret_cast<const float4*>(x)
                     + ((size_t)(b * S_ + ss * SCHUNK_)) * (D_ / 4) + d4;
    float4 acc = make_float4(0.f, 0.f, 0.f, 0.f);
#pragma unroll 16
    for (int s = 0; s < SCHUNK_; ++s) {
        float4 v = __ldcs(&xp[(size_t)s * (D_ / 4)]);
        acc.x += v.x; acc.y += v.y; acc.z += v.z; acc.w += v.w;
    }
    reinterpret_cast<float4*>(g_partial)[(ss * B_ + b) * (D_ / 4) + d4] = acc;
    cudaTriggerProgrammaticLaunchCompletion();
}

// ---------------------------------------------------------------------------
// Kernel B: sims + top-5 per (pool, batch).  grid 128, block 192 (6 warps).
// Pre-sync: collectively prefetch this pool's keys into L2 (overlaps mean).
// ---------------------------------------------------------------------------
__global__ void __launch_bounds__(192) k_sims(const float* __restrict__ skey,
                                              const float* __restrict__ tkey,
                                              float* __restrict__ out) {
    __shared__ __align__(16) float xn[D_];
    __shared__ float sim[POOL_];
    __shared__ float red[8];

    const int pool = blockIdx.x >> 6;         // 0 = s, 1 = t
    const int b    = blockIdx.x & 63;
    const float* keys = pool ? tkey : skey;
    const int simoff  = pool ? OFF_TSIM : OFF_SSIM;

    // ---- PRE-SYNC: prefetch key slice (pool keys: 30*768*4 = 92160 B,
    //      spread over the 64 blocks of this pool; 1440 B each = 90 lines/16)
    {
        const char* base = reinterpret_cast<const char*>(keys);
        int off = b * 1440 + threadIdx.x * 16;
        if (threadIdx.x < 90) l2_prefetch(base + off);
    }

    // Wait for k_mean's stores to be visible, then reduce partials.
    cudaGridDependencySynchronize();

    const int d4 = threadIdx.x;
    float sq;
    {
        float4 s = make_float4(0.f, 0.f, 0.f, 0.f);
#pragma unroll
        for (int s2 = 0; s2 < SS_; ++s2) {
            float4 v = reinterpret_cast<const float4*>(g_partial)[(s2 * B_ + b) * (D_ / 4) + d4];
            s.x += v.x; s.y += v.y; s.z += v.z; s.w += v.w;
        }
        const float scale = 1.f / (float)S_;
        s.x *= scale; s.y *= scale; s.z *= scale; s.w *= scale;
        reinterpret_cast<float4*>(xn)[d4] = s;
        sq = s.x * s.x + s.y * s.y + s.z * s.z + s.w * s.w;
    }

    // block reduce over 6 warps
    const int lane = threadIdx.x & 31, w = threadIdx.x >> 5;
#pragma unroll
    for (int o = 16; o; o >>= 1) sq += __shfl_down_sync(0xffffffffu, sq, o);
    if (lane == 0) red[w] = sq;
    __syncthreads();
    if (w == 0) {
        float v = (lane < 6) ? red[lane] : 0.f;
#pragma unroll
        for (int o = 4; o; o >>= 1) v += __shfl_down_sync(0xffffffffu, v, o);
        if (lane == 0) red[0] = v;
    }
    __syncthreads();
    const float inv = rsqrtf(fmaxf(red[0], 1e-12f));
    {
        float4 v = reinterpret_cast<float4*>(xn)[d4];
        v.x *= inv; v.y *= inv; v.z *= inv; v.w *= inv;
        reinterpret_cast<float4*>(xn)[d4] = v;
    }
    __syncthreads();

    // 30 dots: warp per key round-robin (6 warps x 5 keys); inline key norm
    for (int key = w; key < POOL_; key += 6) {
        const float* kp = keys + key * D_;
        float dot = 0.f, kk = 0.f;
#pragma unroll
        for (int i = 0; i < D_ / 32; ++i) {
            int d = lane + i * 32;
            float kv = __ldg(&kp[d]);
            dot += kv * xn[d];
            kk  += kv * kv;
        }
#pragma unroll
        for (int o = 16; o; o >>= 1) {
            dot += __shfl_down_sync(0xffffffffu, dot, o);
            kk  += __shfl_down_sync(0xffffffffu, kk, o);
        }
        if (lane == 0) {
            float sv = dot * rsqrtf(fmaxf(kk, 1e-12f));
            sim[key] = sv;
            out[simoff + b * POOL_ + key] = sv;
        }
    }
    __syncthreads();

    // top-5 (thread 0); strict '>' keeps lowest index on ties
    if (threadIdx.x == 0) {
        float loc[POOL_];
#pragma unroll
        for (int i = 0; i < POOL_; ++i) loc[i] = sim[i];
        float topsum = 0.f;
#pragma unroll
        for (int k = 0; k < TOPK_; ++k) {
            int   bj = 0;
            float bv = loc[0];
#pragma unroll
            for (int i = 1; i < POOL_; ++i) {
                if (loc[i] > bv) { bv = loc[i]; bj = i; }
            }
            g_idx[pool][b * TOPK_ + k] = bj;
            topsum += bv;
            loc[bj] = -INFINITY;
        }
        if (pool == 0) g_stop[b] = topsum; else g_ttop[b] = topsum;
    }
    // Ensure g_idx/topsum writes precede every thread's trigger.
    __syncthreads();
    cudaTriggerProgrammaticLaunchCompletion();
}

// ---------------------------------------------------------------------------
// Kernel C: gather.  grid 1280 = (pool 2) x (b 64) x (l 2) x (k 5), block 192.
// Pre-sync: collectively prefetch BOTH prompt pools into L2 (overlaps sims /
// mean tail). Post-sync reads are then L2 hits.
// ---------------------------------------------------------------------------
__global__ void __launch_bounds__(192) k_gather(const float* __restrict__ sp,
                                                const float* __restrict__ tp,
                                                float* __restrict__ out) {
    const int bi   = blockIdx.x;
    const int k    = bi % TOPK_;
    const int l    = (bi / TOPK_) % L_;
    const int b    = (bi / (TOPK_ * L_)) % B_;
    const int pool = bi / (TOPK_ * L_ * B_);

    // ---- PRE-SYNC: prefetch prompt pools.
    // Each pool tensor = L*POOL*LEN*D*4 = 1,843,200 B. Combined 3,686,400 B.
    // 1280 blocks x 192 threads x 16 B = 3,932,160 B of prefetch coverage.
    {
        size_t off = ((size_t)bi * 192 + threadIdx.x) * 16;
        const size_t POOLBYTES = (size_t)L_ * POOL_ * LEN_ * D_ * 4;
        if (off < POOLBYTES) {
            l2_prefetch(reinterpret_cast<const char*>(sp) + off);
        } else if (off < 2 * POOLBYTES) {
            l2_prefetch(reinterpret_cast<const char*>(tp) + (off - POOLBYTES));
        }
    }

    cudaGridDependencySynchronize();

    if (bi == 0 && threadIdx.x < 2) {
        const float* g = (threadIdx.x == 0) ? g_stop : g_ttop;
        float s = 0.f;
        for (int i = 0; i < B_; ++i) s += g[i];
        out[(threadIdx.x == 0) ? OFF_SRED : OFF_TRED] = s / (float)B_;
    }

    const int idx = g_idx[pool][b * TOPK_ + k];
    const float* prompts = pool ? tp : sp;
    float* outb = out + (pool ? OFF_TB : OFF_SB);

    const int ROWF4 = D_ / 4;   // 192
    const int col = threadIdx.x;
    const float4* src = reinterpret_cast<const float4*>(
        prompts + ((size_t)((l * POOL_ + idx) * LEN_)) * D_) + col;
    float4* dst = reinterpret_cast<float4*>(
        outb + ((size_t)((l * B_ + b) * (TOPK_ * LEN_) + k * LEN_)) * D_) + col;
#pragma unroll
    for (int t = 0; t < LEN_; ++t) {
        __stcs(&dst[t * ROWF4], __ldg(&src[t * ROWF4]));
    }
}

// ---------------------------------------------------------------------------
// Launch with PDL edges: mean -> sims -> gather
// ---------------------------------------------------------------------------
static void launch_pdl(void* fn, dim3 grid, dim3 block, void** args) {
    cudaLaunchConfig_t cfg = {};
    cfg.gridDim = grid;
    cfg.blockDim = block;
    cfg.dynamicSmemBytes = 0;
    cfg.stream = 0;
    cudaLaunchAttribute attr[1];
    attr[0].id = cudaLaunchAttributeProgrammaticStreamSerialization;
    attr[0].val.programmaticStreamSerializationAllowed = 1;
    cfg.attrs = attr;
    cfg.numAttrs = 1;
    cudaLaunchKernelExC(&cfg, fn, args);
}

extern "C" void kernel_launch(void* const* d_in, const int* in_sizes, int n_in,
                              void* d_out, int out_size) {
    (void)in_sizes; (void)n_in; (void)out_size;
    const float* x_embed  = (const float*)d_in[0];
    const float* s_prompt = (const float*)d_in[1];
    const float* t_prompt = (const float*)d_in[2];
    const float* s_key    = (const float*)d_in[3];
    const float* t_key    = (const float*)d_in[4];
    float* out = (float*)d_out;

    // Primary launch (normal)
    k_mean_partial<<<dim3(B_, SS_), 192>>>(x_embed);

    // Dependent launches with programmatic stream serialization
    {
        void* args[] = { (void*)&s_key, (void*)&t_key, (void*)&out };
        launch_pdl((void*)k_sims, dim3(2 * B_), dim3(192), args);
    }
    {
        void* args[] = { (void*)&s_prompt, (void*)&t_prompt, (void*)&out };
        launch_pdl((void*)k_gather, dim3(2 * B_ * L_ * TOPK_), dim3(192), args);
    }
}